// round 2
// baseline (speedup 1.0000x reference)
#include <cuda_runtime.h>
#include <math.h>

// ---------------- problem constants ----------------
#define DIMX   96
#define HIDX   384
#define DEPTHX 5
#define HEADSX 8
#define INNERX 6144          // 64 * 96
#define DHX    768           // INNERX / HEADSX
#define BX     2
#define NSEQ   512
#define ROWSX  (BX*NSEQ)     // 1024
#define SCALEX 0.125f        // 64^-0.5
#define EPSX   1e-5f

// ---------------- scratch (device globals; no allocation allowed) ----------------
__device__ float g_x  [ROWSX*DIMX];
__device__ float g_h  [ROWSX*DIMX];
__device__ float g_q  [ROWSX*INNERX];
__device__ float g_k  [ROWSX*INNERX];
__device__ float g_v  [ROWSX*INNERX];
__device__ float g_o  [ROWSX*INNERX];
__device__ float g_sim[BX*HEADSX*NSEQ*NSEQ];
__device__ float g_mh [ROWSX*HIDX];

// ---------------- simple copy ----------------
__global__ void copy_kernel(const float* __restrict__ src, float* __restrict__ dst, int n) {
    int i = blockIdx.x * 256 + threadIdx.x;
    if (i < n) dst[i] = src[i];
}

// ---------------- LayerNorm (dim=96), one block per row, in-place safe ----------------
__global__ void ln_kernel(const float* __restrict__ in, const float* __restrict__ g,
                          float* __restrict__ out) {
    int row = blockIdx.x;
    int t   = threadIdx.x;           // 96 threads (3 full warps)
    __shared__ float s[DIMX];
    __shared__ float red[2];
    float v = in[(size_t)row*DIMX + t];
    s[t] = v;
    __syncthreads();
    float a = 0.f;
    if (t < 32) a = s[t] + s[t+32] + s[t+64];
    #pragma unroll
    for (int o = 16; o > 0; o >>= 1) a += __shfl_down_sync(0xffffffffu, a, o);
    if (t == 0) red[0] = a;
    __syncthreads();
    float mu = red[0] * (1.0f / DIMX);
    float d  = v - mu;
    s[t] = d * d;
    __syncthreads();
    float b = 0.f;
    if (t < 32) b = s[t] + s[t+32] + s[t+64];
    #pragma unroll
    for (int o = 16; o > 0; o >>= 1) b += __shfl_down_sync(0xffffffffu, b, o);
    if (t == 0) red[1] = b;
    __syncthreads();
    float var = red[1] * (1.0f / DIMX);
    out[(size_t)row*DIMX + t] = d * rsqrtf(var + EPSX) * (g[t] + 1.0f);
}

// ---------------- row softmax over 512 cols, one block(256) per row ----------------
__global__ void softmax_kernel(float* __restrict__ sim) {
    int row = blockIdx.x;
    float* p = sim + (size_t)row * NSEQ;
    int t = threadIdx.x;                    // 256
    float a = p[t], b = p[t + 256];
    __shared__ float s[256];
    // max
    s[t] = fmaxf(a, b);
    __syncthreads();
    for (int o = 128; o >= 32; o >>= 1) { if (t < o) s[t] = fmaxf(s[t], s[t+o]); __syncthreads(); }
    if (t < 32) {
        float x = s[t];
        #pragma unroll
        for (int o = 16; o > 0; o >>= 1) x = fmaxf(x, __shfl_down_sync(0xffffffffu, x, o));
        if (t == 0) s[0] = x;
    }
    __syncthreads();
    float m = s[0];
    __syncthreads();
    float ea = __expf(a - m) , eb = __expf(b - m);
    // NOTE: use expf for accuracy (fast __expf ~1e-6 rel; fine under 1e-3) — keep precise:
    ea = expf(a - m); eb = expf(b - m);
    s[t] = ea + eb;
    __syncthreads();
    for (int o = 128; o >= 32; o >>= 1) { if (t < o) s[t] += s[t+o]; __syncthreads(); }
    if (t < 32) {
        float x = s[t];
        #pragma unroll
        for (int o = 16; o > 0; o >>= 1) x += __shfl_down_sync(0xffffffffu, x, o);
        if (t == 0) s[0] = x;
    }
    __syncthreads();
    float inv = 1.0f / s[0];
    p[t] = ea * inv;
    p[t + 256] = eb * inv;
}

// ---------------- generic tiled SGEMM: C = alpha*A*B(^T) [+bias][GELU][+res] ----------------
// 128x128x8 tile, 256 threads, 8x8 per thread. Batched via blockIdx.z with
// separate batch/head strides: off = (bz>>3)*s_b + (bz&7)*s_h  (HEADS=8).
template<bool TRANSB, bool BIAS, bool GELU, bool RES>
__global__ __launch_bounds__(256)
void gemm_kernel(const float* __restrict__ A, const float* __restrict__ Bm,
                 const float* __restrict__ bias, const float* __restrict__ res,
                 float* __restrict__ C,
                 int M, int Nn, int K, int lda, int ldb, int ldc,
                 long sA_b, long sA_h, long sB_b, long sB_h, long sC_b, long sC_h,
                 float alpha) {
    const int BM = 128, BN = 128, BK = 8;
    __shared__ float As[BK][BM];
    __shared__ float Bs[BK][BN + 4];

    int bz = blockIdx.z;
    long bb = bz >> 3, hh = bz & 7;
    const float* Ab = A  + bb * sA_b + hh * sA_h;
    const float* Bb = Bm + bb * sB_b + hh * sB_h;
    float*       Cb = C  + bb * sC_b + hh * sC_h;
    const float* Rb = RES ? (res + bb * sC_b + hh * sC_h) : nullptr;

    int bm = blockIdx.y * BM;
    int bn = blockIdx.x * BN;
    int tid = threadIdx.x;
    int tx = tid & 15, ty = tid >> 4;

    float acc[8][8];
    #pragma unroll
    for (int i = 0; i < 8; i++)
        #pragma unroll
        for (int j = 0; j < 8; j++) acc[i][j] = 0.f;

    int arow = tid >> 1, acol = (tid & 1) * 4;          // A: 128 rows x 8 cols
    int brow = tid >> 5, bcol = (tid & 31) * 4;         // B(NN): 8 rows x 128 cols

    for (int k0 = 0; k0 < K; k0 += BK) {
        // ---- A tile (row-major [M,K]) -> As[k][m]
        {
            float4 av = make_float4(0,0,0,0);
            if (bm + arow < M)
                av = *(const float4*)(Ab + (size_t)(bm + arow) * lda + k0 + acol);
            As[acol+0][arow] = av.x; As[acol+1][arow] = av.y;
            As[acol+2][arow] = av.z; As[acol+3][arow] = av.w;
        }
        // ---- B tile -> Bs[k][n]
        if (!TRANSB) {
            float4 bv = make_float4(0,0,0,0);
            if (bn + bcol < Nn)
                bv = *(const float4*)(Bb + (size_t)(k0 + brow) * ldb + bn + bcol);
            *(float4*)&Bs[brow][bcol] = bv;
        } else {
            int nrow = tid >> 1, kcol = (tid & 1) * 4;  // n index, k offset
            float4 bv = make_float4(0,0,0,0);
            if (bn + nrow < Nn)
                bv = *(const float4*)(Bb + (size_t)(bn + nrow) * ldb + k0 + kcol);
            Bs[kcol+0][nrow] = bv.x; Bs[kcol+1][nrow] = bv.y;
            Bs[kcol+2][nrow] = bv.z; Bs[kcol+3][nrow] = bv.w;
        }
        __syncthreads();

        #pragma unroll
        for (int kk = 0; kk < BK; kk++) {
            float ra[8], rb[8];
            #pragma unroll
            for (int i = 0; i < 8; i++) ra[i] = As[kk][ty*8 + i];
            #pragma unroll
            for (int j = 0; j < 8; j++) rb[j] = Bs[kk][tx*8 + j];
            #pragma unroll
            for (int i = 0; i < 8; i++)
                #pragma unroll
                for (int j = 0; j < 8; j++)
                    acc[i][j] = fmaf(ra[i], rb[j], acc[i][j]);
        }
        __syncthreads();
    }

    // ---- epilogue
    #pragma unroll
    for (int i = 0; i < 8; i++) {
        int m = bm + ty*8 + i;
        if (m >= M) continue;
        #pragma unroll
        for (int j = 0; j < 8; j++) {
            int n = bn + tx*8 + j;
            if (n < Nn) {
                float v = acc[i][j] * alpha;
                if (BIAS) v += bias[n];
                if (GELU) v = 0.5f * v * (1.0f + erff(v * 0.70710678118654752f));
                if (RES)  v += Rb[(size_t)m * ldc + n];
                Cb[(size_t)m * ldc + n] = v;
            }
        }
    }
}

// ---------------- host orchestration ----------------
static inline dim3 gemm_grid(int M, int N, int batch) {
    return dim3((N + 127) / 128, (M + 127) / 128, batch);
}

static void attn_step(const float* gam, const float* wq, const float* wk,
                      const float* wv, const float* wo,
                      float* px, float* ph, float* pq, float* pk, float* pv,
                      float* po, float* psim) {
    ln_kernel<<<ROWSX, DIMX>>>(px, gam, ph);
    // q/k/v projections: [1024,96] @ [96,6144]
    gemm_kernel<false,false,false,false><<<gemm_grid(ROWSX, INNERX, 1), 256>>>(
        ph, wq, nullptr, nullptr, pq, ROWSX, INNERX, DIMX, DIMX, INNERX, INNERX,
        0,0,0,0,0,0, 1.0f);
    gemm_kernel<false,false,false,false><<<gemm_grid(ROWSX, INNERX, 1), 256>>>(
        ph, wk, nullptr, nullptr, pk, ROWSX, INNERX, DIMX, DIMX, INNERX, INNERX,
        0,0,0,0,0,0, 1.0f);
    gemm_kernel<false,false,false,false><<<gemm_grid(ROWSX, INNERX, 1), 256>>>(
        ph, wv, nullptr, nullptr, pv, ROWSX, INNERX, DIMX, DIMX, INNERX, INNERX,
        0,0,0,0,0,0, 1.0f);
    // scores: sim[bh] = SCALE * q_bh[512,768] @ k_bh[512,768]^T   (16 batches)
    const long sQKV_b = (long)NSEQ * INNERX;   // per-batch
    const long sQKV_h = DHX;                   // per-head (column offset)
    const long sSIM_h = (long)NSEQ * NSEQ;
    const long sSIM_b = sSIM_h * HEADSX;
    gemm_kernel<true,false,false,false><<<gemm_grid(NSEQ, NSEQ, BX*HEADSX), 256>>>(
        pq, pk, nullptr, nullptr, psim, NSEQ, NSEQ, DHX, INNERX, INNERX, NSEQ,
        sQKV_b, sQKV_h, sQKV_b, sQKV_h, sSIM_b, sSIM_h, SCALEX);
    softmax_kernel<<<BX*HEADSX*NSEQ, 256>>>(psim);
    // context: o[bh] = a[512,512] @ v_bh[512,768]
    gemm_kernel<false,false,false,false><<<gemm_grid(NSEQ, DHX, BX*HEADSX), 256>>>(
        psim, pv, nullptr, nullptr, po, NSEQ, DHX, NSEQ, NSEQ, INNERX, INNERX,
        sSIM_b, sSIM_h, sQKV_b, sQKV_h, sQKV_b, sQKV_h, 1.0f);
    // output proj + residual: x = o @ Wo + x
    gemm_kernel<false,false,false,true><<<gemm_grid(ROWSX, DIMX, 1), 256>>>(
        po, wo, nullptr, px, px, ROWSX, DIMX, INNERX, INNERX, DIMX, DIMX,
        0,0,0,0,0,0, 1.0f);
}

static void mlp_step(const float* gam, const float* w1, const float* b1p,
                     const float* w2, const float* b2p,
                     float* px, float* ph, float* pmh) {
    ln_kernel<<<ROWSX, DIMX>>>(px, gam, ph);
    gemm_kernel<false,true,true,false><<<gemm_grid(ROWSX, HIDX, 1), 256>>>(
        ph, w1, b1p, nullptr, pmh, ROWSX, HIDX, DIMX, DIMX, HIDX, HIDX,
        0,0,0,0,0,0, 1.0f);
    gemm_kernel<false,true,false,true><<<gemm_grid(ROWSX, DIMX, 1), 256>>>(
        pmh, w2, b2p, px, px, ROWSX, DIMX, HIDX, HIDX, DIMX, DIMX,
        0,0,0,0,0,0, 1.0f);
}

extern "C" void kernel_launch(void* const* d_in, const int* in_sizes, int n_in,
                              void* d_out, int out_size) {
    const float* x         = (const float*)d_in[0];
    const float* gam_a     = (const float*)d_in[1];
    const float* Wq        = (const float*)d_in[2];
    const float* Wk        = (const float*)d_in[3];
    const float* Wv        = (const float*)d_in[4];
    const float* Wo        = (const float*)d_in[5];
    const float* gam_m     = (const float*)d_in[6];
    const float* W1        = (const float*)d_in[7];
    const float* b1        = (const float*)d_in[8];
    const float* W2        = (const float*)d_in[9];
    const float* b2        = (const float*)d_in[10];
    const float* gam_mid   = (const float*)d_in[11];
    const float* gam_final = (const float*)d_in[12];
    float* out = (float*)d_out;

    float *px, *ph, *pq, *pk, *pv, *po, *psim, *pmh;
    cudaGetSymbolAddress((void**)&px,   g_x);
    cudaGetSymbolAddress((void**)&ph,   g_h);
    cudaGetSymbolAddress((void**)&pq,   g_q);
    cudaGetSymbolAddress((void**)&pk,   g_k);
    cudaGetSymbolAddress((void**)&pv,   g_v);
    cudaGetSymbolAddress((void**)&po,   g_o);
    cudaGetSymbolAddress((void**)&psim, g_sim);
    cudaGetSymbolAddress((void**)&pmh,  g_mh);

    // x -> g_x
    copy_kernel<<<(ROWSX*DIMX + 255)/256, 256>>>(x, px, ROWSX*DIMX);

    for (int d = 0; d < DEPTHX; d++) {
        const size_t a3 = (size_t)d * 3;           // attn param index base
        const size_t m2 = (size_t)d * 2;           // mlp param index base

        // x = attn(d,0) + x
        attn_step(gam_a + (a3+0)*DIMX,
                  Wq + (a3+0)*(size_t)DIMX*INNERX, Wk + (a3+0)*(size_t)DIMX*INNERX,
                  Wv + (a3+0)*(size_t)DIMX*INNERX, Wo + (a3+0)*(size_t)INNERX*DIMX,
                  px, ph, pq, pk, pv, po, psim);
        // x = mlp(d,0) + x
        mlp_step(gam_m + (m2+0)*DIMX,
                 W1 + (m2+0)*(size_t)DIMX*HIDX, b1 + (m2+0)*HIDX,
                 W2 + (m2+0)*(size_t)HIDX*DIMX, b2 + (m2+0)*DIMX,
                 px, ph, pmh);
        // x = attn(d,1) + x
        attn_step(gam_a + (a3+1)*DIMX,
                  Wq + (a3+1)*(size_t)DIMX*INNERX, Wk + (a3+1)*(size_t)DIMX*INNERX,
                  Wv + (a3+1)*(size_t)DIMX*INNERX, Wo + (a3+1)*(size_t)INNERX*DIMX,
                  px, ph, pq, pk, pv, po, psim);
        // x = attn(d,2) + x
        attn_step(gam_a + (a3+2)*DIMX,
                  Wq + (a3+2)*(size_t)DIMX*INNERX, Wk + (a3+2)*(size_t)DIMX*INNERX,
                  Wv + (a3+2)*(size_t)DIMX*INNERX, Wo + (a3+2)*(size_t)INNERX*DIMX,
                  px, ph, pq, pk, pv, po, psim);
        // x = LN(x, gam_mid[d])   (bare, NO residual; in-place)
        ln_kernel<<<ROWSX, DIMX>>>(px, gam_mid + (size_t)d*DIMX, px);
        // x = mlp(d,1) + x
        mlp_step(gam_m + (m2+1)*DIMX,
                 W1 + (m2+1)*(size_t)DIMX*HIDX, b1 + (m2+1)*HIDX,
                 W2 + (m2+1)*(size_t)HIDX*DIMX, b2 + (m2+1)*DIMX,
                 px, ph, pmh);
    }

    // out = LN(x, gam_final)
    ln_kernel<<<ROWSX, DIMX>>>(px, gam_final, out);
}

// round 3
// speedup vs baseline: 5.7967x; 5.7967x over previous
#include <cuda_runtime.h>
#include <math.h>
#include <stdint.h>

// ---------------- problem constants ----------------
#define DIMX   96
#define HIDX   384
#define DEPTHX 5
#define HEADSX 8
#define INNERX 6144          // 64 * 96
#define DHX    768           // INNERX / HEADSX
#define BX     2
#define NSEQ   512
#define ROWSX  (BX*NSEQ)     // 1024
#define SCALEX 0.125f        // 64^-0.5
#define EPSX   1e-5f
#define SPLIT_WO 16
#define SPLIT_W2 4

// ---------------- scratch (device globals; no allocation allowed) ----------------
__device__ float g_x   [ROWSX*DIMX];
__device__ float g_h   [ROWSX*DIMX];
__device__ float g_q   [ROWSX*INNERX];
__device__ float g_k   [ROWSX*INNERX];
__device__ float g_v   [ROWSX*INNERX];
__device__ float g_o   [ROWSX*INNERX];
__device__ float g_sim [BX*HEADSX*NSEQ*NSEQ];
__device__ float g_mh  [ROWSX*HIDX];
__device__ float g_part[SPLIT_WO*ROWSX*DIMX];   // split-K partials (16 slabs max)

// ---------------- helpers ----------------
__device__ __forceinline__ float to_tf32(float f) {
    uint32_t o;
    asm("cvt.rna.tf32.f32 %0, %1;" : "=r"(o) : "f"(f));
    return __uint_as_float(o);
}

__device__ __forceinline__ void mma_tf32(float& d0, float& d1, float& d2, float& d3,
                                         uint32_t a0, uint32_t a1, uint32_t a2, uint32_t a3,
                                         uint32_t b0, uint32_t b1) {
    asm volatile(
        "mma.sync.aligned.m16n8k8.row.col.f32.tf32.tf32.f32 "
        "{%0,%1,%2,%3}, {%4,%5,%6,%7}, {%8,%9}, {%0,%1,%2,%3};\n"
        : "+f"(d0), "+f"(d1), "+f"(d2), "+f"(d3)
        : "r"(a0), "r"(a1), "r"(a2), "r"(a3), "r"(b0), "r"(b1));
}

// ---------------- simple copy ----------------
__global__ void copy_kernel(const float* __restrict__ src, float* __restrict__ dst, int n) {
    int i = blockIdx.x * 256 + threadIdx.x;
    if (i < n) dst[i] = src[i];
}

// ---------------- LayerNorm (dim=96), one block per row ----------------
__global__ void ln_kernel(const float* __restrict__ in, const float* __restrict__ g,
                          float* __restrict__ out) {
    int row = blockIdx.x;
    int t   = threadIdx.x;           // 96 threads
    __shared__ float s[DIMX];
    __shared__ float red[2];
    float v = in[(size_t)row*DIMX + t];
    s[t] = v;
    __syncthreads();
    float a = 0.f;
    if (t < 32) a = s[t] + s[t+32] + s[t+64];
    #pragma unroll
    for (int o = 16; o > 0; o >>= 1) a += __shfl_down_sync(0xffffffffu, a, o);
    if (t == 0) red[0] = a;
    __syncthreads();
    float mu = red[0] * (1.0f / DIMX);
    float d  = v - mu;
    s[t] = d * d;
    __syncthreads();
    float b = 0.f;
    if (t < 32) b = s[t] + s[t+32] + s[t+64];
    #pragma unroll
    for (int o = 16; o > 0; o >>= 1) b += __shfl_down_sync(0xffffffffu, b, o);
    if (t == 0) red[1] = b;
    __syncthreads();
    float var = red[1] * (1.0f / DIMX);
    out[(size_t)row*DIMX + t] = d * rsqrtf(var + EPSX) * (g[t] + 1.0f);
}

// ---------------- row softmax over 512 cols ----------------
__global__ void softmax_kernel(float* __restrict__ sim) {
    int row = blockIdx.x;
    float* p = sim + (size_t)row * NSEQ;
    int t = threadIdx.x;                    // 256
    float a = p[t], b = p[t + 256];
    __shared__ float s[256];
    s[t] = fmaxf(a, b);
    __syncthreads();
    for (int o = 128; o >= 32; o >>= 1) { if (t < o) s[t] = fmaxf(s[t], s[t+o]); __syncthreads(); }
    if (t < 32) {
        float x = s[t];
        #pragma unroll
        for (int o = 16; o > 0; o >>= 1) x = fmaxf(x, __shfl_down_sync(0xffffffffu, x, o));
        if (t == 0) s[0] = x;
    }
    __syncthreads();
    float m = s[0];
    __syncthreads();
    float ea = expf(a - m), eb = expf(b - m);
    s[t] = ea + eb;
    __syncthreads();
    for (int o = 128; o >= 32; o >>= 1) { if (t < o) s[t] += s[t+o]; __syncthreads(); }
    if (t < 32) {
        float x = s[t];
        #pragma unroll
        for (int o = 16; o > 0; o >>= 1) x += __shfl_down_sync(0xffffffffu, x, o);
        if (t == 0) s[0] = x;
    }
    __syncthreads();
    float inv = 1.0f / s[0];
    p[t] = ea * inv;
    p[t + 256] = eb * inv;
}

// ---------------- tf32 tensor-core GEMM ----------------
// 128x128 block tile, BK=16, 256 threads = 8 warps, warp tile 64x32.
// A row-major [M,K]; B [K,N] (NN) or [N,K] (TRANSB). Batched via blockIdx.z
// (batch*8+head) with separate strides, OR split-K (blockIdx.z = split idx).
// SPLIT: writes partial slab C + z*splitStride, K chunk = K_len at offset z*K_len.
template<bool TRANSB, bool BIAS, bool GELU, bool SPLIT>
__global__ __launch_bounds__(256)
void mma_gemm(const float* __restrict__ A, const float* __restrict__ Bm,
              const float* __restrict__ bias, float* __restrict__ C,
              int M, int Nn, int K_len,
              int lda, int ldb, int ldc,
              long sA_b, long sA_h, long sB_b, long sB_h, long sC_b, long sC_h,
              long splitStride, float alpha) {
    __shared__ float As[128][20];        // m-major, stride 20 (conflict-free)
    __shared__ float Bs[16][136];        // k-major, stride 136 (conflict-free)

    const int tid = threadIdx.x;
    const int bz  = blockIdx.z;
    const float* Ab; const float* Bb; float* Cb;
    int kbase;
    if (SPLIT) {
        Ab = A; Bb = Bm;
        Cb = C + (long)bz * splitStride;
        kbase = bz * K_len;
    } else {
        long bb = bz >> 3, hh = bz & 7;
        Ab = A  + bb * sA_b + hh * sA_h;
        Bb = Bm + bb * sB_b + hh * sB_h;
        Cb = C  + bb * sC_b + hh * sC_h;
        kbase = 0;
    }

    const int bm = blockIdx.y * 128;
    const int bn = blockIdx.x * 128;
    const int wid = tid >> 5;
    const int lane = tid & 31;
    const int gid = lane >> 2;          // 0..7
    const int tg  = lane & 3;           // 0..3
    const int wm = (wid & 1) * 64;      // warp m offset
    const int wn = (wid >> 1) * 32;     // warp n offset

    float acc[4][4][4];
    #pragma unroll
    for (int mi = 0; mi < 4; mi++)
        #pragma unroll
        for (int ni = 0; ni < 4; ni++)
            #pragma unroll
            for (int r = 0; r < 4; r++) acc[mi][ni][r] = 0.f;

    for (int kt = 0; kt < K_len; kt += 16) {
        const int kpos = kbase + kt;
        // ---- load A tile: 128 rows x 16 k, m-major in smem
        #pragma unroll
        for (int r = 0; r < 2; r++) {
            int idx = tid + 256 * r;            // 0..511
            int row = idx >> 2;
            int kc  = (idx & 3) * 4;
            float4 av = make_float4(0,0,0,0);
            if (bm + row < M)
                av = *(const float4*)(Ab + (size_t)(bm + row) * lda + kpos + kc);
            float4 tv = make_float4(to_tf32(av.x), to_tf32(av.y), to_tf32(av.z), to_tf32(av.w));
            *(float4*)&As[row][kc] = tv;
        }
        // ---- load B tile into Bs[k][n]
        if (!TRANSB) {
            #pragma unroll
            for (int r = 0; r < 2; r++) {
                int idx = tid + 256 * r;
                int brow = idx >> 5;            // 0..15
                int nc   = (idx & 31) * 4;
                float4 bv = make_float4(0,0,0,0);
                if (bn + nc < Nn)
                    bv = *(const float4*)(Bb + (size_t)(kpos + brow) * ldb + bn + nc);
                float4 tv = make_float4(to_tf32(bv.x), to_tf32(bv.y), to_tf32(bv.z), to_tf32(bv.w));
                *(float4*)&Bs[brow][nc] = tv;
            }
        } else {
            #pragma unroll
            for (int r = 0; r < 2; r++) {
                int idx = tid + 256 * r;
                int nrow = idx >> 2;            // 0..127
                int kc   = (idx & 3) * 4;
                float4 bv = make_float4(0,0,0,0);
                if (bn + nrow < Nn)
                    bv = *(const float4*)(Bb + (size_t)(bn + nrow) * ldb + kpos + kc);
                Bs[kc+0][nrow] = to_tf32(bv.x);
                Bs[kc+1][nrow] = to_tf32(bv.y);
                Bs[kc+2][nrow] = to_tf32(bv.z);
                Bs[kc+3][nrow] = to_tf32(bv.w);
            }
        }
        __syncthreads();

        // ---- compute: two k8 sub-steps
        #pragma unroll
        for (int ks = 0; ks < 16; ks += 8) {
            uint32_t af[4][4];
            #pragma unroll
            for (int mi = 0; mi < 4; mi++) {
                int mrow = wm + mi * 16 + gid;
                af[mi][0] = __float_as_uint(As[mrow    ][ks + tg    ]);
                af[mi][1] = __float_as_uint(As[mrow + 8][ks + tg    ]);
                af[mi][2] = __float_as_uint(As[mrow    ][ks + tg + 4]);
                af[mi][3] = __float_as_uint(As[mrow + 8][ks + tg + 4]);
            }
            uint32_t bf[4][2];
            #pragma unroll
            for (int ni = 0; ni < 4; ni++) {
                int ncol = wn + ni * 8 + gid;
                bf[ni][0] = __float_as_uint(Bs[ks + tg    ][ncol]);
                bf[ni][1] = __float_as_uint(Bs[ks + tg + 4][ncol]);
            }
            #pragma unroll
            for (int mi = 0; mi < 4; mi++)
                #pragma unroll
                for (int ni = 0; ni < 4; ni++)
                    mma_tf32(acc[mi][ni][0], acc[mi][ni][1], acc[mi][ni][2], acc[mi][ni][3],
                             af[mi][0], af[mi][1], af[mi][2], af[mi][3],
                             bf[ni][0], bf[ni][1]);
        }
        __syncthreads();
    }

    // ---- epilogue
    #pragma unroll
    for (int mi = 0; mi < 4; mi++) {
        int m0 = bm + wm + mi * 16 + gid;
        #pragma unroll
        for (int ni = 0; ni < 4; ni++) {
            int n0 = bn + wn + ni * 8 + tg * 2;
            #pragma unroll
            for (int rr = 0; rr < 2; rr++) {     // rr=0: row m0, rr=1: row m0+8
                int m = m0 + rr * 8;
                if (m >= M) continue;
                #pragma unroll
                for (int cc = 0; cc < 2; cc++) {
                    int n = n0 + cc;
                    if (n >= Nn) continue;
                    float v = acc[mi][ni][rr * 2 + cc] * alpha;
                    if (BIAS) v += bias[n];
                    if (GELU) v = 0.5f * v * (1.0f + erff(v * 0.70710678118654752f));
                    Cb[(size_t)m * ldc + n] = v;
                }
            }
        }
    }
}

// ---------------- split-K reduction: x += sum(part slabs) [+bias] ----------------
__global__ void reduce_kernel(const float* __restrict__ part, int S,
                              const float* __restrict__ bias, float* __restrict__ x) {
    int i = blockIdx.x * 256 + threadIdx.x;
    const int MN = ROWSX * DIMX;
    if (i >= MN) return;
    float a = 0.f;
    for (int s = 0; s < S; s++) a += part[(size_t)s * MN + i];
    if (bias) a += bias[i % DIMX];
    x[i] += a;
}

// ---------------- host orchestration ----------------
static void attn_step(const float* gam, const float* wq, const float* wk,
                      const float* wv, const float* wo,
                      float* px, float* ph, float* pq, float* pk, float* pv,
                      float* po, float* psim, float* ppart) {
    ln_kernel<<<ROWSX, DIMX>>>(px, gam, ph);
    // q/k/v projections: [1024,96] @ [96,6144]
    dim3 gqkv(INNERX/128, ROWSX/128, 1);
    mma_gemm<false,false,false,false><<<gqkv, 256>>>(
        ph, wq, nullptr, pq, ROWSX, INNERX, DIMX, DIMX, INNERX, INNERX,
        0,0,0,0,0,0, 0, 1.0f);
    mma_gemm<false,false,false,false><<<gqkv, 256>>>(
        ph, wk, nullptr, pk, ROWSX, INNERX, DIMX, DIMX, INNERX, INNERX,
        0,0,0,0,0,0, 0, 1.0f);
    mma_gemm<false,false,false,false><<<gqkv, 256>>>(
        ph, wv, nullptr, pv, ROWSX, INNERX, DIMX, DIMX, INNERX, INNERX,
        0,0,0,0,0,0, 0, 1.0f);
    // scores: sim[bh] = SCALE * q_bh[512,768] @ k_bh[512,768]^T   (16 batches)
    const long sQKV_b = (long)NSEQ * INNERX;
    const long sQKV_h = DHX;
    const long sSIM_h = (long)NSEQ * NSEQ;
    const long sSIM_b = sSIM_h * HEADSX;
    mma_gemm<true,false,false,false><<<dim3(NSEQ/128, NSEQ/128, BX*HEADSX), 256>>>(
        pq, pk, nullptr, psim, NSEQ, NSEQ, DHX, INNERX, INNERX, NSEQ,
        sQKV_b, sQKV_h, sQKV_b, sQKV_h, sSIM_b, sSIM_h, 0, SCALEX);
    softmax_kernel<<<BX*HEADSX*NSEQ, 256>>>(psim);
    // context: o[bh] = a[512,512] @ v_bh[512,768]
    mma_gemm<false,false,false,false><<<dim3(DHX/128, NSEQ/128, BX*HEADSX), 256>>>(
        psim, pv, nullptr, po, NSEQ, DHX, NSEQ, NSEQ, INNERX, INNERX,
        sSIM_b, sSIM_h, sQKV_b, sQKV_h, sQKV_b, sQKV_h, 0, 1.0f);
    // output proj split-K: part[s] = o @ Wo[k-chunk s]; then x += sum(part)
    mma_gemm<false,false,false,true><<<dim3(1, ROWSX/128, SPLIT_WO), 256>>>(
        po, wo, nullptr, ppart, ROWSX, DIMX, INNERX/SPLIT_WO, INNERX, DIMX, DIMX,
        0,0,0,0,0,0, (long)ROWSX*DIMX, 1.0f);
    reduce_kernel<<<(ROWSX*DIMX + 255)/256, 256>>>(ppart, SPLIT_WO, nullptr, px);
}

static void mlp_step(const float* gam, const float* w1, const float* b1p,
                     const float* w2, const float* b2p,
                     float* px, float* ph, float* pmh, float* ppart) {
    ln_kernel<<<ROWSX, DIMX>>>(px, gam, ph);
    mma_gemm<false,true,true,false><<<dim3(HIDX/128, ROWSX/128, 1), 256>>>(
        ph, w1, b1p, pmh, ROWSX, HIDX, DIMX, DIMX, HIDX, HIDX,
        0,0,0,0,0,0, 0, 1.0f);
    mma_gemm<false,false,false,true><<<dim3(1, ROWSX/128, SPLIT_W2), 256>>>(
        pmh, w2, nullptr, ppart, ROWSX, DIMX, HIDX/SPLIT_W2, HIDX, DIMX, DIMX,
        0,0,0,0,0,0, (long)ROWSX*DIMX, 1.0f);
    reduce_kernel<<<(ROWSX*DIMX + 255)/256, 256>>>(ppart, SPLIT_W2, b2p, px);
}

extern "C" void kernel_launch(void* const* d_in, const int* in_sizes, int n_in,
                              void* d_out, int out_size) {
    const float* x         = (const float*)d_in[0];
    const float* gam_a     = (const float*)d_in[1];
    const float* Wq        = (const float*)d_in[2];
    const float* Wk        = (const float*)d_in[3];
    const float* Wv        = (const float*)d_in[4];
    const float* Wo        = (const float*)d_in[5];
    const float* gam_m     = (const float*)d_in[6];
    const float* W1        = (const float*)d_in[7];
    const float* b1        = (const float*)d_in[8];
    const float* W2        = (const float*)d_in[9];
    const float* b2        = (const float*)d_in[10];
    const float* gam_mid   = (const float*)d_in[11];
    const float* gam_final = (const float*)d_in[12];
    float* out = (float*)d_out;

    float *px, *ph, *pq, *pk, *pv, *po, *psim, *pmh, *ppart;
    cudaGetSymbolAddress((void**)&px,    g_x);
    cudaGetSymbolAddress((void**)&ph,    g_h);
    cudaGetSymbolAddress((void**)&pq,    g_q);
    cudaGetSymbolAddress((void**)&pk,    g_k);
    cudaGetSymbolAddress((void**)&pv,    g_v);
    cudaGetSymbolAddress((void**)&po,    g_o);
    cudaGetSymbolAddress((void**)&psim,  g_sim);
    cudaGetSymbolAddress((void**)&pmh,   g_mh);
    cudaGetSymbolAddress((void**)&ppart, g_part);

    copy_kernel<<<(ROWSX*DIMX + 255)/256, 256>>>(x, px, ROWSX*DIMX);

    for (int d = 0; d < DEPTHX; d++) {
        const size_t a3 = (size_t)d * 3;
        const size_t m2 = (size_t)d * 2;

        attn_step(gam_a + (a3+0)*DIMX,
                  Wq + (a3+0)*(size_t)DIMX*INNERX, Wk + (a3+0)*(size_t)DIMX*INNERX,
                  Wv + (a3+0)*(size_t)DIMX*INNERX, Wo + (a3+0)*(size_t)INNERX*DIMX,
                  px, ph, pq, pk, pv, po, psim, ppart);
        mlp_step(gam_m + (m2+0)*DIMX,
                 W1 + (m2+0)*(size_t)DIMX*HIDX, b1 + (m2+0)*HIDX,
                 W2 + (m2+0)*(size_t)HIDX*DIMX, b2 + (m2+0)*DIMX,
                 px, ph, pmh, ppart);
        attn_step(gam_a + (a3+1)*DIMX,
                  Wq + (a3+1)*(size_t)DIMX*INNERX, Wk + (a3+1)*(size_t)DIMX*INNERX,
                  Wv + (a3+1)*(size_t)DIMX*INNERX, Wo + (a3+1)*(size_t)INNERX*DIMX,
                  px, ph, pq, pk, pv, po, psim, ppart);
        attn_step(gam_a + (a3+2)*DIMX,
                  Wq + (a3+2)*(size_t)DIMX*INNERX, Wk + (a3+2)*(size_t)DIMX*INNERX,
                  Wv + (a3+2)*(size_t)DIMX*INNERX, Wo + (a3+2)*(size_t)INNERX*DIMX,
                  px, ph, pq, pk, pv, po, psim, ppart);
        ln_kernel<<<ROWSX, DIMX>>>(px, gam_mid + (size_t)d*DIMX, px);
        mlp_step(gam_m + (m2+1)*DIMX,
                 W1 + (m2+1)*(size_t)DIMX*HIDX, b1 + (m2+1)*HIDX,
                 W2 + (m2+1)*(size_t)HIDX*DIMX, b2 + (m2+1)*DIMX,
                 px, ph, pmh, ppart);
    }

    ln_kernel<<<ROWSX, DIMX>>>(px, gam_final, out);
}

// round 4
// speedup vs baseline: 7.8528x; 1.3547x over previous
#include <cuda_runtime.h>
#include <math.h>
#include <stdint.h>

// ---------------- problem constants ----------------
#define DIMX   96
#define HIDX   384
#define DEPTHX 5
#define HEADSX 8
#define INNERX 6144          // 64 * 96
#define DHX    768           // INNERX / HEADSX
#define BX     2
#define NSEQ   512
#define ROWSX  (BX*NSEQ)     // 1024
#define SCALEX 0.125f        // 64^-0.5
#define EPSX   1e-5f
#define SPLIT_WO 16
#define SPLIT_W2 4
#define STAGES 3

// ---------------- scratch (device globals; no allocation allowed) ----------------
__device__ float g_x   [ROWSX*DIMX];
__device__ float g_h   [ROWSX*DIMX];
__device__ float g_q   [ROWSX*INNERX];
__device__ float g_k   [ROWSX*INNERX];
__device__ float g_v   [ROWSX*INNERX];
__device__ float g_o   [ROWSX*INNERX];
__device__ float g_sim [BX*HEADSX*NSEQ*NSEQ];
__device__ float g_mh  [ROWSX*HIDX];
__device__ float g_part[SPLIT_WO*ROWSX*DIMX];

// ---------------- cp.async helpers ----------------
__device__ __forceinline__ void cp16(uint32_t smem_addr, const float* gptr, bool pred) {
    int sz = pred ? 16 : 0;
    asm volatile("cp.async.cg.shared.global [%0], [%1], 16, %2;\n"
                 :: "r"(smem_addr), "l"(gptr), "r"(sz));
}
__device__ __forceinline__ void cp_commit() {
    asm volatile("cp.async.commit_group;\n");
}
template<int N>
__device__ __forceinline__ void cp_wait() {
    asm volatile("cp.async.wait_group %0;\n" :: "n"(N));
}

__device__ __forceinline__ void mma_tf32(float& d0, float& d1, float& d2, float& d3,
                                         uint32_t a0, uint32_t a1, uint32_t a2, uint32_t a3,
                                         uint32_t b0, uint32_t b1) {
    asm volatile(
        "mma.sync.aligned.m16n8k8.row.col.f32.tf32.tf32.f32 "
        "{%0,%1,%2,%3}, {%4,%5,%6,%7}, {%8,%9}, {%0,%1,%2,%3};\n"
        : "+f"(d0), "+f"(d1), "+f"(d2), "+f"(d3)
        : "r"(a0), "r"(a1), "r"(a2), "r"(a3), "r"(b0), "r"(b1));
}

// ---------------- simple copy ----------------
__global__ void copy_kernel(const float* __restrict__ src, float* __restrict__ dst, int n) {
    int i = blockIdx.x * 256 + threadIdx.x;
    if (i < n) dst[i] = src[i];
}

// ---------------- LayerNorm (dim=96), one block per row ----------------
__global__ void ln_kernel(const float* __restrict__ in, const float* __restrict__ g,
                          float* __restrict__ out) {
    int row = blockIdx.x;
    int t   = threadIdx.x;           // 96 threads
    __shared__ float s[DIMX];
    __shared__ float red[2];
    float v = in[(size_t)row*DIMX + t];
    s[t] = v;
    __syncthreads();
    float a = 0.f;
    if (t < 32) a = s[t] + s[t+32] + s[t+64];
    #pragma unroll
    for (int o = 16; o > 0; o >>= 1) a += __shfl_down_sync(0xffffffffu, a, o);
    if (t == 0) red[0] = a;
    __syncthreads();
    float mu = red[0] * (1.0f / DIMX);
    float d  = v - mu;
    s[t] = d * d;
    __syncthreads();
    float b = 0.f;
    if (t < 32) b = s[t] + s[t+32] + s[t+64];
    #pragma unroll
    for (int o = 16; o > 0; o >>= 1) b += __shfl_down_sync(0xffffffffu, b, o);
    if (t == 0) red[1] = b;
    __syncthreads();
    float var = red[1] * (1.0f / DIMX);
    out[(size_t)row*DIMX + t] = d * rsqrtf(var + EPSX) * (g[t] + 1.0f);
}

// ---------------- row softmax over 512 cols ----------------
__global__ void softmax_kernel(float* __restrict__ sim) {
    int row = blockIdx.x;
    float* p = sim + (size_t)row * NSEQ;
    int t = threadIdx.x;                    // 256
    float a = p[t], b = p[t + 256];
    __shared__ float s[256];
    s[t] = fmaxf(a, b);
    __syncthreads();
    for (int o = 128; o >= 32; o >>= 1) { if (t < o) s[t] = fmaxf(s[t], s[t+o]); __syncthreads(); }
    if (t < 32) {
        float x = s[t];
        #pragma unroll
        for (int o = 16; o > 0; o >>= 1) x = fmaxf(x, __shfl_down_sync(0xffffffffu, x, o));
        if (t == 0) s[0] = x;
    }
    __syncthreads();
    float m = s[0];
    __syncthreads();
    float ea = expf(a - m), eb = expf(b - m);
    s[t] = ea + eb;
    __syncthreads();
    for (int o = 128; o >= 32; o >>= 1) { if (t < o) s[t] += s[t+o]; __syncthreads(); }
    if (t < 32) {
        float x = s[t];
        #pragma unroll
        for (int o = 16; o > 0; o >>= 1) x += __shfl_down_sync(0xffffffffu, x, o);
        if (t == 0) s[0] = x;
    }
    __syncthreads();
    float inv = 1.0f / s[0];
    p[t] = ea * inv;
    p[t + 256] = eb * inv;
}

// ---------------- tf32 tensor-core GEMM, 3-stage cp.async pipeline ----------------
// 128x128 block tile, BK=16, 256 threads = 8 warps, warp tile 64x32.
// A row-major [M,K]. B: [K,N] (NN, smem k-major stride 136) or [N,K]
// (TRANSB, smem n-major stride 20 — row-major [N,K] IS col-major KxN, so no
// transpose needed for mma.row.col). Raw fp32 bits fed to tf32 HMMA (HW
// truncation; no cvt). Batched via blockIdx.z or split-K.
template<bool TRANSB, bool BIAS, bool GELU, bool SPLIT>
__global__ __launch_bounds__(256, 2)
void mma_gemm(const float* __restrict__ A, const float* __restrict__ Bm,
              const float* __restrict__ bias, float* __restrict__ C,
              int M, int Nn, int K_len,
              int lda, int ldb, int ldc,
              long sA_b, long sA_h, long sB_b, long sB_h, long sC_b, long sC_h,
              long splitStride, float alpha) {
    __shared__ float As[STAGES][2560];   // [row*20 + k]
    __shared__ float Bs[STAGES][2560];   // NN: [k*136 + n] ; TRANSB: [n*20 + k]

    const int tid = threadIdx.x;
    const int bz  = blockIdx.z;
    const float* Ab; const float* Bb; float* Cb;
    int kbase;
    if (SPLIT) {
        Ab = A; Bb = Bm;
        Cb = C + (long)bz * splitStride;
        kbase = bz * K_len;
    } else {
        long bb = bz >> 3, hh = bz & 7;
        Ab = A  + bb * sA_b + hh * sA_h;
        Bb = Bm + bb * sB_b + hh * sB_h;
        Cb = C  + bb * sC_b + hh * sC_h;
        kbase = 0;
    }

    const int bm = blockIdx.y * 128;
    const int bn = blockIdx.x * 128;
    const int wid = tid >> 5;
    const int lane = tid & 31;
    const int gid = lane >> 2;          // 0..7
    const int tg  = lane & 3;           // 0..3
    const int wm = (wid & 1) * 64;
    const int wn = (wid >> 1) * 32;

    const uint32_t as0 = (uint32_t)__cvta_generic_to_shared(&As[0][0]);
    const uint32_t bs0 = (uint32_t)__cvta_generic_to_shared(&Bs[0][0]);

    // per-thread load coordinates (2 chunks of 16B each per tile per operand)
    const int a_row0 = tid >> 2;               // 0..63
    const int a_kc   = (tid & 3) * 4;          // 0,4,8,12
    // NN B: 16 rows x 128 cols -> idx>>5 = k row, (idx&31)*4 = n col
    const int bn_k0  = tid >> 5;               // 0..7
    const int bn_nc  = (tid & 31) * 4;

    const int nt = K_len / 16;

    float acc[4][4][4];
    #pragma unroll
    for (int mi = 0; mi < 4; mi++)
        #pragma unroll
        for (int ni = 0; ni < 4; ni++)
            #pragma unroll
            for (int r = 0; r < 4; r++) acc[mi][ni][r] = 0.f;

    // ---- tile loader (issues 4 cp.async per thread, one commit group)
    auto load_tile = [&](int t, int s) {
        const int kpos = kbase + t * 16;
        // A: rows a_row0, a_row0+64
        #pragma unroll
        for (int r = 0; r < 2; r++) {
            int row = a_row0 + 64 * r;
            const float* src = Ab + (size_t)(bm + row) * lda + kpos + a_kc;
            cp16(as0 + (s * 2560 + row * 20 + a_kc) * 4, src, (bm + row) < M);
        }
        if (!TRANSB) {
            #pragma unroll
            for (int r = 0; r < 2; r++) {
                int krow = bn_k0 + 8 * r;
                const float* src = Bb + (size_t)(kpos + krow) * ldb + bn + bn_nc;
                cp16(bs0 + (s * 2560 + krow * 136 + bn_nc) * 4, src, (bn + bn_nc) < Nn);
            }
        } else {
            #pragma unroll
            for (int r = 0; r < 2; r++) {
                int nrow = a_row0 + 64 * r;
                const float* src = Bb + (size_t)(bn + nrow) * ldb + kpos + a_kc;
                cp16(bs0 + (s * 2560 + nrow * 20 + a_kc) * 4, src, (bn + nrow) < Nn);
            }
        }
        cp_commit();
    };

    // prefetch STAGES-1 tiles
    #pragma unroll
    for (int s = 0; s < STAGES - 1; s++)
        if (s < nt) load_tile(s, s);

    for (int t = 0; t < nt; t++) {
        const int cur = t % STAGES;
        if (t + 1 < nt) cp_wait<STAGES - 2>(); else cp_wait<0>();
        __syncthreads();
        if (t + STAGES - 1 < nt) load_tile(t + STAGES - 1, (t + STAGES - 1) % STAGES);

        const float* as = As[cur];
        const float* bs = Bs[cur];
        #pragma unroll
        for (int ks = 0; ks < 16; ks += 8) {
            uint32_t af[4][4];
            #pragma unroll
            for (int mi = 0; mi < 4; mi++) {
                int mrow = wm + mi * 16 + gid;
                af[mi][0] = __float_as_uint(as[(mrow    ) * 20 + ks + tg    ]);
                af[mi][1] = __float_as_uint(as[(mrow + 8) * 20 + ks + tg    ]);
                af[mi][2] = __float_as_uint(as[(mrow    ) * 20 + ks + tg + 4]);
                af[mi][3] = __float_as_uint(as[(mrow + 8) * 20 + ks + tg + 4]);
            }
            uint32_t bf[4][2];
            #pragma unroll
            for (int ni = 0; ni < 4; ni++) {
                int ncol = wn + ni * 8 + gid;
                if (!TRANSB) {
                    bf[ni][0] = __float_as_uint(bs[(ks + tg    ) * 136 + ncol]);
                    bf[ni][1] = __float_as_uint(bs[(ks + tg + 4) * 136 + ncol]);
                } else {
                    bf[ni][0] = __float_as_uint(bs[ncol * 20 + ks + tg    ]);
                    bf[ni][1] = __float_as_uint(bs[ncol * 20 + ks + tg + 4]);
                }
            }
            #pragma unroll
            for (int mi = 0; mi < 4; mi++)
                #pragma unroll
                for (int ni = 0; ni < 4; ni++)
                    mma_tf32(acc[mi][ni][0], acc[mi][ni][1], acc[mi][ni][2], acc[mi][ni][3],
                             af[mi][0], af[mi][1], af[mi][2], af[mi][3],
                             bf[ni][0], bf[ni][1]);
        }
        __syncthreads();
    }

    // ---- epilogue (M always a multiple of 128 here; guard N only)
    #pragma unroll
    for (int mi = 0; mi < 4; mi++) {
        int m0 = bm + wm + mi * 16 + gid;
        #pragma unroll
        for (int ni = 0; ni < 4; ni++) {
            int n0 = bn + wn + ni * 8 + tg * 2;
            #pragma unroll
            for (int rr = 0; rr < 2; rr++) {
                int m = m0 + rr * 8;
                #pragma unroll
                for (int cc = 0; cc < 2; cc++) {
                    int n = n0 + cc;
                    if (n < Nn) {
                        float v = acc[mi][ni][rr * 2 + cc] * alpha;
                        if (BIAS) v += bias[n];
                        if (GELU) v = 0.5f * v * (1.0f + erff(v * 0.70710678118654752f));
                        Cb[(size_t)m * ldc + n] = v;
                    }
                }
            }
        }
    }
}

// ---------------- split-K reduction: x += sum(part slabs) [+bias] ----------------
__global__ void reduce_kernel(const float* __restrict__ part, int S,
                              const float* __restrict__ bias, float* __restrict__ x) {
    int i = blockIdx.x * 256 + threadIdx.x;
    const int MN = ROWSX * DIMX;
    if (i >= MN) return;
    float a = 0.f;
    for (int s = 0; s < S; s++) a += part[(size_t)s * MN + i];
    if (bias) a += bias[i % DIMX];
    x[i] += a;
}

// ---------------- host orchestration ----------------
static void attn_step(const float* gam, const float* wq, const float* wk,
                      const float* wv, const float* wo,
                      float* px, float* ph, float* pq, float* pk, float* pv,
                      float* po, float* psim, float* ppart) {
    ln_kernel<<<ROWSX, DIMX>>>(px, gam, ph);
    dim3 gqkv(INNERX/128, ROWSX/128, 1);
    mma_gemm<false,false,false,false><<<gqkv, 256>>>(
        ph, wq, nullptr, pq, ROWSX, INNERX, DIMX, DIMX, INNERX, INNERX,
        0,0,0,0,0,0, 0, 1.0f);
    mma_gemm<false,false,false,false><<<gqkv, 256>>>(
        ph, wk, nullptr, pk, ROWSX, INNERX, DIMX, DIMX, INNERX, INNERX,
        0,0,0,0,0,0, 0, 1.0f);
    mma_gemm<false,false,false,false><<<gqkv, 256>>>(
        ph, wv, nullptr, pv, ROWSX, INNERX, DIMX, DIMX, INNERX, INNERX,
        0,0,0,0,0,0, 0, 1.0f);
    const long sQKV_b = (long)NSEQ * INNERX;
    const long sQKV_h = DHX;
    const long sSIM_h = (long)NSEQ * NSEQ;
    const long sSIM_b = sSIM_h * HEADSX;
    mma_gemm<true,false,false,false><<<dim3(NSEQ/128, NSEQ/128, BX*HEADSX), 256>>>(
        pq, pk, nullptr, psim, NSEQ, NSEQ, DHX, INNERX, INNERX, NSEQ,
        sQKV_b, sQKV_h, sQKV_b, sQKV_h, sSIM_b, sSIM_h, 0, SCALEX);
    softmax_kernel<<<BX*HEADSX*NSEQ, 256>>>(psim);
    mma_gemm<false,false,false,false><<<dim3(DHX/128, NSEQ/128, BX*HEADSX), 256>>>(
        psim, pv, nullptr, po, NSEQ, DHX, NSEQ, NSEQ, INNERX, INNERX,
        sSIM_b, sSIM_h, sQKV_b, sQKV_h, sQKV_b, sQKV_h, 0, 1.0f);
    mma_gemm<false,false,false,true><<<dim3(1, ROWSX/128, SPLIT_WO), 256>>>(
        po, wo, nullptr, ppart, ROWSX, DIMX, INNERX/SPLIT_WO, INNERX, DIMX, DIMX,
        0,0,0,0,0,0, (long)ROWSX*DIMX, 1.0f);
    reduce_kernel<<<(ROWSX*DIMX + 255)/256, 256>>>(ppart, SPLIT_WO, nullptr, px);
}

static void mlp_step(const float* gam, const float* w1, const float* b1p,
                     const float* w2, const float* b2p,
                     float* px, float* ph, float* pmh, float* ppart) {
    ln_kernel<<<ROWSX, DIMX>>>(px, gam, ph);
    mma_gemm<false,true,true,false><<<dim3(HIDX/128, ROWSX/128, 1), 256>>>(
        ph, w1, b1p, pmh, ROWSX, HIDX, DIMX, DIMX, HIDX, HIDX,
        0,0,0,0,0,0, 0, 1.0f);
    mma_gemm<false,false,false,true><<<dim3(1, ROWSX/128, SPLIT_W2), 256>>>(
        pmh, w2, nullptr, ppart, ROWSX, DIMX, HIDX/SPLIT_W2, HIDX, DIMX, DIMX,
        0,0,0,0,0,0, (long)ROWSX*DIMX, 1.0f);
    reduce_kernel<<<(ROWSX*DIMX + 255)/256, 256>>>(ppart, SPLIT_W2, b2p, px);
}

extern "C" void kernel_launch(void* const* d_in, const int* in_sizes, int n_in,
                              void* d_out, int out_size) {
    const float* x         = (const float*)d_in[0];
    const float* gam_a     = (const float*)d_in[1];
    const float* Wq        = (const float*)d_in[2];
    const float* Wk        = (const float*)d_in[3];
    const float* Wv        = (const float*)d_in[4];
    const float* Wo        = (const float*)d_in[5];
    const float* gam_m     = (const float*)d_in[6];
    const float* W1        = (const float*)d_in[7];
    const float* b1        = (const float*)d_in[8];
    const float* W2        = (const float*)d_in[9];
    const float* b2        = (const float*)d_in[10];
    const float* gam_mid   = (const float*)d_in[11];
    const float* gam_final = (const float*)d_in[12];
    float* out = (float*)d_out;

    float *px, *ph, *pq, *pk, *pv, *po, *psim, *pmh, *ppart;
    cudaGetSymbolAddress((void**)&px,    g_x);
    cudaGetSymbolAddress((void**)&ph,    g_h);
    cudaGetSymbolAddress((void**)&pq,    g_q);
    cudaGetSymbolAddress((void**)&pk,    g_k);
    cudaGetSymbolAddress((void**)&pv,    g_v);
    cudaGetSymbolAddress((void**)&po,    g_o);
    cudaGetSymbolAddress((void**)&psim,  g_sim);
    cudaGetSymbolAddress((void**)&pmh,   g_mh);
    cudaGetSymbolAddress((void**)&ppart, g_part);

    copy_kernel<<<(ROWSX*DIMX + 255)/256, 256>>>(x, px, ROWSX*DIMX);

    for (int d = 0; d < DEPTHX; d++) {
        const size_t a3 = (size_t)d * 3;
        const size_t m2 = (size_t)d * 2;

        attn_step(gam_a + (a3+0)*DIMX,
                  Wq + (a3+0)*(size_t)DIMX*INNERX, Wk + (a3+0)*(size_t)DIMX*INNERX,
                  Wv + (a3+0)*(size_t)DIMX*INNERX, Wo + (a3+0)*(size_t)INNERX*DIMX,
                  px, ph, pq, pk, pv, po, psim, ppart);
        mlp_step(gam_m + (m2+0)*DIMX,
                 W1 + (m2+0)*(size_t)DIMX*HIDX, b1 + (m2+0)*HIDX,
                 W2 + (m2+0)*(size_t)HIDX*DIMX, b2 + (m2+0)*DIMX,
                 px, ph, pmh, ppart);
        attn_step(gam_a + (a3+1)*DIMX,
                  Wq + (a3+1)*(size_t)DIMX*INNERX, Wk + (a3+1)*(size_t)DIMX*INNERX,
                  Wv + (a3+1)*(size_t)DIMX*INNERX, Wo + (a3+1)*(size_t)INNERX*DIMX,
                  px, ph, pq, pk, pv, po, psim, ppart);
        attn_step(gam_a + (a3+2)*DIMX,
                  Wq + (a3+2)*(size_t)DIMX*INNERX, Wk + (a3+2)*(size_t)DIMX*INNERX,
                  Wv + (a3+2)*(size_t)DIMX*INNERX, Wo + (a3+2)*(size_t)INNERX*DIMX,
                  px, ph, pq, pk, pv, po, psim, ppart);
        ln_kernel<<<ROWSX, DIMX>>>(px, gam_mid + (size_t)d*DIMX, px);
        mlp_step(gam_m + (m2+1)*DIMX,
                 W1 + (m2+1)*(size_t)DIMX*HIDX, b1 + (m2+1)*HIDX,
                 W2 + (m2+1)*(size_t)HIDX*DIMX, b2 + (m2+1)*DIMX,
                 px, ph, pmh, ppart);
    }

    ln_kernel<<<ROWSX, DIMX>>>(px, gam_final, out);
}

// round 6
// speedup vs baseline: 8.1093x; 1.0327x over previous
#include <cuda_runtime.h>
#include <math.h>
#include <stdint.h>

// ---------------- problem constants ----------------
#define DIMX   96
#define HIDX   384
#define DEPTHX 5
#define HEADSX 8
#define INNERX 6144          // 64 * 96
#define DHX    768           // INNERX / HEADSX
#define BX     2
#define NSEQ   512
#define ROWSX  (BX*NSEQ)     // 1024
#define NQKV   (3*INNERX)    // 18432
#define SCALEX 0.125f
#define EPSX   1e-5f
#define SPLIT_WO 16
#define SPLIT_W2 4
#define STAGES 4
#define SMEM_BYTES (STAGES*2560*2*4)   // 81920

// ---------------- scratch (device globals; no allocation allowed) ----------------
__device__ float g_x   [ROWSX*DIMX];
__device__ float g_h   [ROWSX*DIMX];
__device__ float g_qkv [ROWSX*NQKV];              // q | k | v  (ld = 18432)
__device__ float g_o   [ROWSX*INNERX];
__device__ float g_sim [BX*HEADSX*NSEQ*NSEQ];
__device__ float g_mh  [ROWSX*HIDX];
__device__ float g_part[SPLIT_WO*ROWSX*DIMX];
// pre-rounded (tf32-rna) weights
__device__ float g_wqkv[15*DIMX*NQKV];            // packed [l][k][Wq|Wk|Wv]
__device__ float g_wo  [15*INNERX*DIMX];
__device__ float g_w1  [10*DIMX*HIDX];
__device__ float g_w2  [10*HIDX*DIMX];

// ---------------- helpers ----------------
__device__ __forceinline__ float to_tf32(float f) {
    uint32_t o;
    asm("cvt.rna.tf32.f32 %0, %1;" : "=r"(o) : "f"(f));
    return __uint_as_float(o);
}
__device__ __forceinline__ void cp16(uint32_t smem_addr, const float* gptr, bool pred) {
    int sz = pred ? 16 : 0;
    asm volatile("cp.async.cg.shared.global [%0], [%1], 16, %2;\n"
                 :: "r"(smem_addr), "l"(gptr), "r"(sz));
}
__device__ __forceinline__ void cp_commit() { asm volatile("cp.async.commit_group;\n"); }
template<int N>
__device__ __forceinline__ void cp_wait() { asm volatile("cp.async.wait_group %0;\n" :: "n"(N)); }

__device__ __forceinline__ void mma_tf32(float& d0, float& d1, float& d2, float& d3,
                                         uint32_t a0, uint32_t a1, uint32_t a2, uint32_t a3,
                                         uint32_t b0, uint32_t b1) {
    asm volatile(
        "mma.sync.aligned.m16n8k8.row.col.f32.tf32.tf32.f32 "
        "{%0,%1,%2,%3}, {%4,%5,%6,%7}, {%8,%9}, {%0,%1,%2,%3};\n"
        : "+f"(d0), "+f"(d1), "+f"(d2), "+f"(d3)
        : "r"(a0), "r"(a1), "r"(a2), "r"(a3), "r"(b0), "r"(b1));
}

// ---------------- weight conversion (once per launch; graph-captured) ----------------
__global__ void pack_qkv_kernel(const float* __restrict__ Wq, const float* __restrict__ Wk,
                                const float* __restrict__ Wv, float* __restrict__ dst, int n) {
    int i = blockIdx.x * 256 + threadIdx.x;
    if (i >= n) return;
    int j  = i % NQKV;
    int lk = i / NQKV;              // l*96 + k, 0..1439
    float v;
    if (j < INNERX)           v = Wq[(size_t)lk * INNERX + j];
    else if (j < 2*INNERX)    v = Wk[(size_t)lk * INNERX + (j - INNERX)];
    else                      v = Wv[(size_t)lk * INNERX + (j - 2*INNERX)];
    dst[i] = to_tf32(v);
}
__global__ void rna_copy_kernel(const float* __restrict__ src, float* __restrict__ dst, int n) {
    int i = blockIdx.x * 256 + threadIdx.x;
    if (i < n) dst[i] = to_tf32(src[i]);
}
__global__ void copy_kernel(const float* __restrict__ src, float* __restrict__ dst, int n) {
    int i = blockIdx.x * 256 + threadIdx.x;
    if (i < n) dst[i] = src[i];
}

// ---------------- LayerNorm (dim=96), one block per row ----------------
template<bool ROUND>
__global__ void ln_kernel(const float* __restrict__ in, const float* __restrict__ g,
                          float* __restrict__ out) {
    int row = blockIdx.x;
    int t   = threadIdx.x;
    __shared__ float s[DIMX];
    __shared__ float red[2];
    float v = in[(size_t)row*DIMX + t];
    s[t] = v;
    __syncthreads();
    float a = 0.f;
    if (t < 32) a = s[t] + s[t+32] + s[t+64];
    #pragma unroll
    for (int o = 16; o > 0; o >>= 1) a += __shfl_down_sync(0xffffffffu, a, o);
    if (t == 0) red[0] = a;
    __syncthreads();
    float mu = red[0] * (1.0f / DIMX);
    float d  = v - mu;
    s[t] = d * d;
    __syncthreads();
    float b = 0.f;
    if (t < 32) b = s[t] + s[t+32] + s[t+64];
    #pragma unroll
    for (int o = 16; o > 0; o >>= 1) b += __shfl_down_sync(0xffffffffu, b, o);
    if (t == 0) red[1] = b;
    __syncthreads();
    float var = red[1] * (1.0f / DIMX);
    float r = d * rsqrtf(var + EPSX) * (g[t] + 1.0f);
    out[(size_t)row*DIMX + t] = ROUND ? to_tf32(r) : r;
}

// ---------------- fused split-K reduce + residual + LayerNorm ----------------
// val = x + [bias] + sum(part slabs). REPLACE: x = ln(val,g).
// else: x = val; out = [round](ln(val,g)).
template<bool ROUND, bool REPLACE, bool HASBIAS>
__global__ void red_ln_kernel(const float* __restrict__ part, int S,
                              const float* __restrict__ bias,
                              float* __restrict__ x, const float* __restrict__ g,
                              float* __restrict__ out) {
    const int MN = ROWSX * DIMX;
    int row = blockIdx.x;
    int t   = threadIdx.x;
    size_t idx = (size_t)row*DIMX + t;
    float val = x[idx];
    if (HASBIAS) val += bias[t];
    for (int s = 0; s < S; s++) val += part[(size_t)s*MN + idx];
    __shared__ float sm[DIMX];
    __shared__ float red[2];
    sm[t] = val;
    __syncthreads();
    float a = 0.f;
    if (t < 32) a = sm[t] + sm[t+32] + sm[t+64];
    #pragma unroll
    for (int o = 16; o > 0; o >>= 1) a += __shfl_down_sync(0xffffffffu, a, o);
    if (t == 0) red[0] = a;
    __syncthreads();
    float mu = red[0] * (1.0f / DIMX);
    float d  = val - mu;
    sm[t] = d * d;
    __syncthreads();
    float b = 0.f;
    if (t < 32) b = sm[t] + sm[t+32] + sm[t+64];
    #pragma unroll
    for (int o = 16; o > 0; o >>= 1) b += __shfl_down_sync(0xffffffffu, b, o);
    if (t == 0) red[1] = b;
    __syncthreads();
    float var = red[1] * (1.0f / DIMX);
    float lnv = d * rsqrtf(var + EPSX) * (g[t] + 1.0f);
    if (REPLACE) {
        x[idx] = lnv;
    } else {
        x[idx] = val;
        out[idx] = ROUND ? to_tf32(lnv) : lnv;
    }
}

// ---------------- row softmax over 512 cols (rounds output to tf32) ----------------
__global__ void softmax_kernel(float* __restrict__ sim) {
    int row = blockIdx.x;
    float* p = sim + (size_t)row * NSEQ;
    int t = threadIdx.x;                    // 256
    float a = p[t], b = p[t + 256];
    __shared__ float s[256];
    s[t] = fmaxf(a, b);
    __syncthreads();
    for (int o = 128; o >= 32; o >>= 1) { if (t < o) s[t] = fmaxf(s[t], s[t+o]); __syncthreads(); }
    if (t < 32) {
        float x = s[t];
        #pragma unroll
        for (int o = 16; o > 0; o >>= 1) x = fmaxf(x, __shfl_down_sync(0xffffffffu, x, o));
        if (t == 0) s[0] = x;
    }
    __syncthreads();
    float m = s[0];
    __syncthreads();
    float ea = expf(a - m), eb = expf(b - m);
    s[t] = ea + eb;
    __syncthreads();
    for (int o = 128; o >= 32; o >>= 1) { if (t < o) s[t] += s[t+o]; __syncthreads(); }
    if (t < 32) {
        float x = s[t];
        #pragma unroll
        for (int o = 16; o > 0; o >>= 1) x += __shfl_down_sync(0xffffffffu, x, o);
        if (t == 0) s[0] = x;
    }
    __syncthreads();
    float inv = 1.0f / s[0];
    p[t]       = to_tf32(ea * inv);
    p[t + 256] = to_tf32(eb * inv);
}

// ---------------- tf32 tensor-core GEMM, 4-stage cp.async, 1 sync/k-tile ----------------
// 128x128 block tile, BK=16, 256 threads, warp tile 64x32.
// Inputs are pre-rounded tf32 values stored as fp32; raw bits fed to HMMA.
template<bool TRANSB, bool BIAS, bool GELU, bool SPLIT, bool ROUND>
__global__ __launch_bounds__(256, 2)
void mma_gemm(const float* __restrict__ A, const float* __restrict__ Bm,
              const float* __restrict__ bias, float* __restrict__ C,
              int M, int Nn, int K_len,
              int lda, int ldb, int ldc,
              long sA_b, long sA_h, long sB_b, long sB_h, long sC_b, long sC_h,
              long splitStride, float alpha) {
    extern __shared__ float smem[];
    float* Asm = smem;                     // [STAGES][2560]: [row*20+k]
    float* Bsm = smem + STAGES*2560;       // NN: [k*136+n]; TRANSB: [n*20+k]

    const int tid = threadIdx.x;
    const int bz  = blockIdx.z;
    const float* Ab; const float* Bb; float* Cb;
    int kbase;
    if (SPLIT) {
        Ab = A; Bb = Bm;
        Cb = C + (long)bz * splitStride;
        kbase = bz * K_len;
    } else {
        long bb = bz >> 3, hh = bz & 7;
        Ab = A  + bb * sA_b + hh * sA_h;
        Bb = Bm + bb * sB_b + hh * sB_h;
        Cb = C  + bb * sC_b + hh * sC_h;
        kbase = 0;
    }

    const int bm = blockIdx.y * 128;
    const int bn = blockIdx.x * 128;
    const int wid = tid >> 5;
    const int lane = tid & 31;
    const int gid = lane >> 2;
    const int tg  = lane & 3;
    const int wm = (wid & 1) * 64;
    const int wn = (wid >> 1) * 32;

    const uint32_t as0 = (uint32_t)__cvta_generic_to_shared(Asm);
    const uint32_t bs0 = (uint32_t)__cvta_generic_to_shared(Bsm);

    const int a_row0 = tid >> 2;
    const int a_kc   = (tid & 3) * 4;
    const int bn_k0  = tid >> 5;
    const int bn_nc  = (tid & 31) * 4;

    const int nt = K_len / 16;

    float acc[4][4][4];
    #pragma unroll
    for (int mi = 0; mi < 4; mi++)
        #pragma unroll
        for (int ni = 0; ni < 4; ni++)
            #pragma unroll
            for (int r = 0; r < 4; r++) acc[mi][ni][r] = 0.f;

    auto load_tile = [&](int t, int s) {
        const int kpos = kbase + t * 16;
        #pragma unroll
        for (int r = 0; r < 2; r++) {
            int row = a_row0 + 64 * r;
            const float* src = Ab + (size_t)(bm + row) * lda + kpos + a_kc;
            cp16(as0 + (s * 2560 + row * 20 + a_kc) * 4, src, (bm + row) < M);
        }
        if (!TRANSB) {
            #pragma unroll
            for (int r = 0; r < 2; r++) {
                int krow = bn_k0 + 8 * r;
                const float* src = Bb + (size_t)(kpos + krow) * ldb + bn + bn_nc;
                cp16(bs0 + (s * 2560 + krow * 136 + bn_nc) * 4, src, (bn + bn_nc) < Nn);
            }
        } else {
            #pragma unroll
            for (int r = 0; r < 2; r++) {
                int nrow = a_row0 + 64 * r;
                const float* src = Bb + (size_t)(bn + nrow) * ldb + kpos + a_kc;
                cp16(bs0 + (s * 2560 + nrow * 20 + a_kc) * 4, src, (bn + nrow) < Nn);
            }
        }
        cp_commit();
    };

    #pragma unroll
    for (int s = 0; s < STAGES - 1; s++)
        if (s < nt) load_tile(s, s);

    for (int t = 0; t < nt; t++) {
        const int cur = t & 3;
        if (t + 3 <= nt)      cp_wait<2>();
        else if (t + 2 <= nt) cp_wait<1>();
        else                  cp_wait<0>();
        __syncthreads();
        if (t + 3 < nt) load_tile(t + 3, (t + 3) & 3);

        const float* as = Asm + cur * 2560;
        const float* bs = Bsm + cur * 2560;
        #pragma unroll
        for (int ks = 0; ks < 16; ks += 8) {
            uint32_t af[4][4];
            #pragma unroll
            for (int mi = 0; mi < 4; mi++) {
                int mrow = wm + mi * 16 + gid;
                af[mi][0] = __float_as_uint(as[(mrow    ) * 20 + ks + tg    ]);
                af[mi][1] = __float_as_uint(as[(mrow + 8) * 20 + ks + tg    ]);
                af[mi][2] = __float_as_uint(as[(mrow    ) * 20 + ks + tg + 4]);
                af[mi][3] = __float_as_uint(as[(mrow + 8) * 20 + ks + tg + 4]);
            }
            uint32_t bf[4][2];
            #pragma unroll
            for (int ni = 0; ni < 4; ni++) {
                int ncol = wn + ni * 8 + gid;
                if (!TRANSB) {
                    bf[ni][0] = __float_as_uint(bs[(ks + tg    ) * 136 + ncol]);
                    bf[ni][1] = __float_as_uint(bs[(ks + tg + 4) * 136 + ncol]);
                } else {
                    bf[ni][0] = __float_as_uint(bs[ncol * 20 + ks + tg    ]);
                    bf[ni][1] = __float_as_uint(bs[ncol * 20 + ks + tg + 4]);
                }
            }
            #pragma unroll
            for (int mi = 0; mi < 4; mi++)
                #pragma unroll
                for (int ni = 0; ni < 4; ni++)
                    mma_tf32(acc[mi][ni][0], acc[mi][ni][1], acc[mi][ni][2], acc[mi][ni][3],
                             af[mi][0], af[mi][1], af[mi][2], af[mi][3],
                             bf[ni][0], bf[ni][1]);
        }
        __syncthreads();
    }

    #pragma unroll
    for (int mi = 0; mi < 4; mi++) {
        int m0 = bm + wm + mi * 16 + gid;
        #pragma unroll
        for (int ni = 0; ni < 4; ni++) {
            int n0 = bn + wn + ni * 8 + tg * 2;
            #pragma unroll
            for (int rr = 0; rr < 2; rr++) {
                int m = m0 + rr * 8;
                #pragma unroll
                for (int cc = 0; cc < 2; cc++) {
                    int n = n0 + cc;
                    if (n < Nn) {
                        float v = acc[mi][ni][rr * 2 + cc] * alpha;
                        if (BIAS) v += bias[n];
                        if (GELU) v = 0.5f * v * (1.0f + erff(v * 0.70710678118654752f));
                        if (ROUND) v = to_tf32(v);
                        Cb[(size_t)m * ldc + n] = v;
                    }
                }
            }
        }
    }
}

// ---------------- host orchestration ----------------
extern "C" void kernel_launch(void* const* d_in, const int* in_sizes, int n_in,
                              void* d_out, int out_size) {
    const float* x         = (const float*)d_in[0];
    const float* gam_a     = (const float*)d_in[1];
    const float* Wq        = (const float*)d_in[2];
    const float* Wk        = (const float*)d_in[3];
    const float* Wv        = (const float*)d_in[4];
    const float* Wo        = (const float*)d_in[5];
    const float* gam_m     = (const float*)d_in[6];
    const float* W1        = (const float*)d_in[7];
    const float* b1        = (const float*)d_in[8];
    const float* W2        = (const float*)d_in[9];
    const float* b2        = (const float*)d_in[10];
    const float* gam_mid   = (const float*)d_in[11];
    const float* gam_final = (const float*)d_in[12];
    float* out = (float*)d_out;

    float *px, *ph, *pqkv, *po, *psim, *pmh, *ppart, *pwqkv, *pwo, *pw1, *pw2;
    cudaGetSymbolAddress((void**)&px,    g_x);
    cudaGetSymbolAddress((void**)&ph,    g_h);
    cudaGetSymbolAddress((void**)&pqkv,  g_qkv);
    cudaGetSymbolAddress((void**)&po,    g_o);
    cudaGetSymbolAddress((void**)&psim,  g_sim);
    cudaGetSymbolAddress((void**)&pmh,   g_mh);
    cudaGetSymbolAddress((void**)&ppart, g_part);
    cudaGetSymbolAddress((void**)&pwqkv, g_wqkv);
    cudaGetSymbolAddress((void**)&pwo,   g_wo);
    cudaGetSymbolAddress((void**)&pw1,   g_w1);
    cudaGetSymbolAddress((void**)&pw2,   g_w2);

    // allow 80KB dynamic smem on all GEMM instantiations (idempotent)
    cudaFuncSetAttribute(mma_gemm<false,false,false,false,true>,
                         cudaFuncAttributeMaxDynamicSharedMemorySize, SMEM_BYTES);
    cudaFuncSetAttribute(mma_gemm<true,false,false,false,false>,
                         cudaFuncAttributeMaxDynamicSharedMemorySize, SMEM_BYTES);
    cudaFuncSetAttribute(mma_gemm<false,false,false,true,false>,
                         cudaFuncAttributeMaxDynamicSharedMemorySize, SMEM_BYTES);
    cudaFuncSetAttribute(mma_gemm<false,true,true,false,true>,
                         cudaFuncAttributeMaxDynamicSharedMemorySize, SMEM_BYTES);

    // ---- weight preprocessing (pre-rounded tf32) ----
    {
        int nq = 15*DIMX*NQKV;
        pack_qkv_kernel<<<(nq + 255)/256, 256>>>(Wq, Wk, Wv, pwqkv, nq);
        int no = 15*INNERX*DIMX;
        rna_copy_kernel<<<(no + 255)/256, 256>>>(Wo, pwo, no);
        int n1 = 10*DIMX*HIDX;
        rna_copy_kernel<<<(n1 + 255)/256, 256>>>(W1, pw1, n1);
        int n2 = 10*HIDX*DIMX;
        rna_copy_kernel<<<(n2 + 255)/256, 256>>>(W2, pw2, n2);
    }

    copy_kernel<<<(ROWSX*DIMX + 255)/256, 256>>>(x, px, ROWSX*DIMX);
    // first attention pre-norm
    ln_kernel<true><<<ROWSX, DIMX>>>(px, gam_a + 0, ph);

    const long sQKV_b = (long)NSEQ * NQKV;
    const long sQKV_h = DHX;
    const long sSIM_h = (long)NSEQ * NSEQ;
    const long sSIM_b = sSIM_h * HEADSX;
    const long sO_b   = (long)NSEQ * INNERX;
    const long sO_h   = DHX;

    auto do_attn = [&](int widx) {       // widx = 3*d + s, weights; h already prepared
        const float* wqkv_l = pwqkv + (size_t)widx * DIMX * NQKV;
        const float* wo_l   = pwo   + (size_t)widx * INNERX * DIMX;
        // fused QKV: [1024,96] @ [96,18432] -> g_qkv (rounded)
        mma_gemm<false,false,false,false,true><<<dim3(NQKV/128, ROWSX/128, 1), 256, SMEM_BYTES>>>(
            ph, wqkv_l, nullptr, pqkv, ROWSX, NQKV, DIMX, DIMX, NQKV, NQKV,
            0,0,0,0,0,0, 0, 1.0f);
        // scores = SCALE * q @ k^T per (b,h)
        mma_gemm<true,false,false,false,false><<<dim3(NSEQ/128, NSEQ/128, BX*HEADSX), 256, SMEM_BYTES>>>(
            pqkv, pqkv + INNERX, nullptr, psim, NSEQ, NSEQ, DHX, NQKV, NQKV, NSEQ,
            sQKV_b, sQKV_h, sQKV_b, sQKV_h, sSIM_b, sSIM_h, 0, SCALEX);
        softmax_kernel<<<BX*HEADSX*NSEQ, 256>>>(psim);
        // context = a @ v per (b,h) -> g_o (rounded)
        mma_gemm<false,false,false,false,true><<<dim3(DHX/128, NSEQ/128, BX*HEADSX), 256, SMEM_BYTES>>>(
            psim, pqkv + 2*INNERX, nullptr, po, NSEQ, DHX, NSEQ, NSEQ, NQKV, INNERX,
            sSIM_b, sSIM_h, sQKV_b, sQKV_h, sO_b, sO_h, 0, 1.0f);
        // Wo split-K partials
        mma_gemm<false,false,false,true,false><<<dim3(1, ROWSX/128, SPLIT_WO), 256, SMEM_BYTES>>>(
            po, wo_l, nullptr, ppart, ROWSX, DIMX, INNERX/SPLIT_WO, INNERX, DIMX, DIMX,
            0,0,0,0,0,0, (long)ROWSX*DIMX, 1.0f);
    };
    auto do_mlp_gemms = [&](int midx) {  // midx = 2*d + s; h prepared
        const float* w1_l = pw1 + (size_t)midx * DIMX * HIDX;
        const float* w2_l = pw2 + (size_t)midx * HIDX * DIMX;
        mma_gemm<false,true,true,false,true><<<dim3(HIDX/128, ROWSX/128, 1), 256, SMEM_BYTES>>>(
            ph, w1_l, b1 + (size_t)midx * HIDX, pmh, ROWSX, HIDX, DIMX, DIMX, HIDX, HIDX,
            0,0,0,0,0,0, 0, 1.0f);
        mma_gemm<false,false,false,true,false><<<dim3(1, ROWSX/128, SPLIT_W2), 256, SMEM_BYTES>>>(
            pmh, w2_l, nullptr, ppart, ROWSX, DIMX, HIDX/SPLIT_W2, HIDX, DIMX, DIMX,
            0,0,0,0,0,0, (long)ROWSX*DIMX, 1.0f);
    };

    for (int d = 0; d < DEPTHX; d++) {
        // attn 0 ; then fuse reduce + ln(gam_m[2d]) -> h
        do_attn(3*d + 0);
        red_ln_kernel<true,false,false><<<ROWSX, DIMX>>>(
            ppart, SPLIT_WO, nullptr, px, gam_m + (size_t)(2*d+0)*DIMX, ph);
        // mlp 0 ; fuse reduce(+b2) + ln(gam_a[d,1]) -> h
        do_mlp_gemms(2*d + 0);
        red_ln_kernel<true,false,true><<<ROWSX, DIMX>>>(
            ppart, SPLIT_W2, b2 + (size_t)(2*d+0)*DIMX, px, gam_a + (size_t)(3*d+1)*DIMX, ph);
        // attn 1 ; fuse reduce + ln(gam_a[d,2]) -> h
        do_attn(3*d + 1);
        red_ln_kernel<true,false,false><<<ROWSX, DIMX>>>(
            ppart, SPLIT_WO, nullptr, px, gam_a + (size_t)(3*d+2)*DIMX, ph);
        // attn 2 ; fuse reduce + bare mid-LN (x replaced, fp32)
        do_attn(3*d + 2);
        red_ln_kernel<false,true,false><<<ROWSX, DIMX>>>(
            ppart, SPLIT_WO, nullptr, px, gam_mid + (size_t)d*DIMX, px);
        // mlp 1 pre-norm
        ln_kernel<true><<<ROWSX, DIMX>>>(px, gam_m + (size_t)(2*d+1)*DIMX, ph);
        do_mlp_gemms(2*d + 1);
        if (d < DEPTHX - 1) {
            red_ln_kernel<true,false,true><<<ROWSX, DIMX>>>(
                ppart, SPLIT_W2, b2 + (size_t)(2*d+1)*DIMX, px, gam_a + (size_t)(3*d+3)*DIMX, ph);
        } else {
            // final: x += mlp out, out = LN(x, gam_final) in fp32
            red_ln_kernel<false,false,true><<<ROWSX, DIMX>>>(
                ppart, SPLIT_W2, b2 + (size_t)(2*d+1)*DIMX, px, gam_final, out);
        }
    }
}